// round 1
// baseline (speedup 1.0000x reference)
#include <cuda_runtime.h>

#define BB 8
#define NN 16384
#define DD 512
#define MV 8
#define SS 128                      // N-splits in pass 1
#define RPS (NN / SS)               // rows per split = 128
#define SCALE_F 0.1f
#define EPS_F 1e-5f

// Scratch (no cudaMalloc allowed)
__device__ float g_partial[BB][SS][DD];   // 2 MB
__device__ float g_SW2[BB][MV][DD];       // 128 KB  (SCALE * M^T-folded Wo)
__device__ float g_F[BB][DD];             // 16 KB   (SCALE*(bp-fold + bo))

// ---------------------------------------------------------------------------
// Pass 1: partial sums of x over N (for the mean field)
// grid (SS, BB), 128 threads. Each block sums RPS rows of 512 floats.
// ---------------------------------------------------------------------------
__global__ void k_partial(const float* __restrict__ x) {
    int b = blockIdx.y, s = blockIdx.x, t = threadIdx.x;  // t in [0,128)
    const float4* xp = (const float4*)(x + ((size_t)b * NN + (size_t)s * RPS) * DD);
    float4 a0 = make_float4(0.f, 0.f, 0.f, 0.f);
    float4 a1 = make_float4(0.f, 0.f, 0.f, 0.f);
#pragma unroll 4
    for (int r = 0; r < RPS; r += 2) {
        float4 v0 = xp[(size_t)r * 128 + t];
        float4 v1 = xp[(size_t)(r + 1) * 128 + t];
        a0.x += v0.x; a0.y += v0.y; a0.z += v0.z; a0.w += v0.w;
        a1.x += v1.x; a1.y += v1.y; a1.z += v1.z; a1.w += v1.w;
    }
    a0.x += a1.x; a0.y += a1.y; a0.z += a1.z; a0.w += a1.w;
    ((float4*)&g_partial[b][s][0])[t] = a0;
}

// ---------------------------------------------------------------------------
// Pass 2: per-batch prep. One block per batch, 512 threads.
// mean -> meanfield_mv -> Cayley-fold M -> SW2 = SCALE*(M @ Wo^T),
// F = SCALE*(bp-fold + bo).
// ---------------------------------------------------------------------------
__global__ void k_prep(const float* __restrict__ Wm, const float* __restrict__ bm,
                       const float* __restrict__ Wo, const float* __restrict__ bp,
                       const float* __restrict__ bo) {
    __shared__ float mean_s[DD];
    __shared__ float mf_s[MV];
    __shared__ float M_s[MV][MV];
    int b = blockIdx.x, t = threadIdx.x;  // 512 threads

    float acc = 0.f;
    for (int s = 0; s < SS; ++s) acc += g_partial[b][s][t];
    mean_s[t] = acc * (1.0f / NN);
    __syncthreads();

    int w = t >> 5, l = t & 31;
    if (w < MV) {
        float p = 0.f;
#pragma unroll
        for (int c = 0; c < 16; ++c) p += mean_s[l + 32 * c] * Wm[w * DD + l + 32 * c];
#pragma unroll
        for (int o = 16; o; o >>= 1) p += __shfl_xor_sync(0xffffffffu, p, o);
        if (l == 0) mf_s[w] = p + bm[w];
    }
    __syncthreads();

    if (t < 64) {
        // Cl(3,0) Cayley: masks in basis order, idx maps mask -> basis index
        const int maskT[8] = {0, 1, 2, 4, 3, 5, 6, 7};
        const int idxT[8]  = {0, 1, 2, 4, 3, 5, 6, 7};
        int i = t >> 3, j = t & 7;
        int a = maskT[i], bj = maskT[j];
        int sgn = 0, aa = a >> 1;
        while (aa) { sgn += __popc(aa & bj); aa >>= 1; }
        int k = idxT[a ^ bj];
        // For fixed i, j<->k is a bijection: direct assignment, no accumulation.
        M_s[i][k] = ((sgn & 1) ? -1.f : 1.f) * mf_s[j];
    }
    __syncthreads();

    float wo[8];
#pragma unroll
    for (int k = 0; k < 8; ++k) wo[k] = Wo[t * 8 + k];
    float fb = 0.f;
#pragma unroll
    for (int i = 0; i < MV; ++i) {
        float w2 = 0.f;
#pragma unroll
        for (int k = 0; k < 8; ++k) w2 += M_s[i][k] * wo[k];
        g_SW2[b][i][t] = SCALE_F * w2;
        fb += bp[i] * w2;
    }
    g_F[b][t] = SCALE_F * (fb + bo[t]);
}

// ---------------------------------------------------------------------------
// Pass 3: fused main kernel. grid (64, 8), 256 threads (8 warps).
// Each block: 256 rows of its batch. Each warp: 32 rows, 2 per iteration.
// Lane d-mapping: d = c*128 + l*4 + j (conflict-free float4 LDS, coalesced LDG).
// ---------------------------------------------------------------------------
__global__ void __launch_bounds__(256, 2)
k_main(const float* __restrict__ x, const float* __restrict__ Wp,
       const float* __restrict__ gamma, const float* __restrict__ beta,
       float* __restrict__ y) {
    __shared__ float Wp_s[MV * DD];
    __shared__ float SW2_s[MV * DD];
    __shared__ float F_s[DD], gm_s[DD], bt_s[DD];

    int b = blockIdx.y, t = threadIdx.x;
    const float* sw2g = &g_SW2[b][0][0];
    for (int i = t; i < MV * DD; i += 256) { Wp_s[i] = Wp[i]; SW2_s[i] = sw2g[i]; }
    for (int i = t; i < DD; i += 256) { F_s[i] = g_F[b][i]; gm_s[i] = gamma[i]; bt_s[i] = beta[i]; }
    __syncthreads();

    int w = t >> 5, l = t & 31;
    size_t base = ((size_t)b * NN + (size_t)blockIdx.x * 256 + (size_t)w * 32) * DD;
    const float4* xp = (const float4*)(x + base);
    float4* yp = (float4*)(y + base);

    for (int it = 0; it < 16; ++it) {
        const float4* xa = xp + (size_t)(it * 2) * 128;
        const float4* xb = xa + 128;
        float4 va[4], vb[4];
#pragma unroll
        for (int c = 0; c < 4; ++c) { va[c] = xa[c * 32 + l]; vb[c] = xb[c * 32 + l]; }

        // 8 dot-products per row (partial, per-lane over its 16 d's)
        float pa[8], pb[8];
#pragma unroll
        for (int i = 0; i < MV; ++i) {
            float sa = 0.f, sb = 0.f;
#pragma unroll
            for (int c = 0; c < 4; ++c) {
                float4 wv = *(const float4*)&Wp_s[i * DD + c * 128 + l * 4];
                sa += va[c].x * wv.x + va[c].y * wv.y + va[c].z * wv.z + va[c].w * wv.w;
                sb += vb[c].x * wv.x + vb[c].y * wv.y + vb[c].z * wv.z + vb[c].w * wv.w;
            }
            pa[i] = sa; pb[i] = sb;
        }
        // butterfly reduce 8 values x 2 rows (all lanes end with full sums)
#pragma unroll
        for (int o = 16; o; o >>= 1) {
#pragma unroll
            for (int i = 0; i < MV; ++i) {
                pa[i] += __shfl_xor_sync(0xffffffffu, pa[i], o);
                pb[i] += __shfl_xor_sync(0xffffffffu, pb[i], o);
            }
        }

        // y = x + F + sum_i pm[i]*SW2[i][:]   (SCALE already folded)
#pragma unroll
        for (int c = 0; c < 4; ++c) {
            float4 f4 = *(const float4*)&F_s[c * 128 + l * 4];
            va[c].x += f4.x; va[c].y += f4.y; va[c].z += f4.z; va[c].w += f4.w;
            vb[c].x += f4.x; vb[c].y += f4.y; vb[c].z += f4.z; vb[c].w += f4.w;
        }
#pragma unroll
        for (int i = 0; i < MV; ++i) {
            float ai = pa[i], bi = pb[i];
#pragma unroll
            for (int c = 0; c < 4; ++c) {
                float4 s4 = *(const float4*)&SW2_s[i * DD + c * 128 + l * 4];
                va[c].x += ai * s4.x; va[c].y += ai * s4.y; va[c].z += ai * s4.z; va[c].w += ai * s4.w;
                vb[c].x += bi * s4.x; vb[c].y += bi * s4.y; vb[c].z += bi * s4.z; vb[c].w += bi * s4.w;
            }
        }

        // LayerNorm stats (biased var), 4-value butterfly
        float sa = 0.f, qa = 0.f, sb = 0.f, qb = 0.f;
#pragma unroll
        for (int c = 0; c < 4; ++c) {
            sa += va[c].x + va[c].y + va[c].z + va[c].w;
            qa += va[c].x * va[c].x + va[c].y * va[c].y + va[c].z * va[c].z + va[c].w * va[c].w;
            sb += vb[c].x + vb[c].y + vb[c].z + vb[c].w;
            qb += vb[c].x * vb[c].x + vb[c].y * vb[c].y + vb[c].z * vb[c].z + vb[c].w * vb[c].w;
        }
#pragma unroll
        for (int o = 16; o; o >>= 1) {
            sa += __shfl_xor_sync(0xffffffffu, sa, o);
            qa += __shfl_xor_sync(0xffffffffu, qa, o);
            sb += __shfl_xor_sync(0xffffffffu, sb, o);
            qb += __shfl_xor_sync(0xffffffffu, qb, o);
        }
        float mua = sa * (1.f / DD), mub = sb * (1.f / DD);
        float ra = rsqrtf(qa * (1.f / DD) - mua * mua + EPS_F);
        float rb = rsqrtf(qb * (1.f / DD) - mub * mub + EPS_F);

#pragma unroll
        for (int c = 0; c < 4; ++c) {
            float4 g4 = *(const float4*)&gm_s[c * 128 + l * 4];
            float4 b4 = *(const float4*)&bt_s[c * 128 + l * 4];
            float4 oa, ob;
            oa.x = g4.x * (va[c].x - mua) * ra + b4.x;
            oa.y = g4.y * (va[c].y - mua) * ra + b4.y;
            oa.z = g4.z * (va[c].z - mua) * ra + b4.z;
            oa.w = g4.w * (va[c].w - mua) * ra + b4.w;
            ob.x = g4.x * (vb[c].x - mub) * rb + b4.x;
            ob.y = g4.y * (vb[c].y - mub) * rb + b4.y;
            ob.z = g4.z * (vb[c].z - mub) * rb + b4.z;
            ob.w = g4.w * (vb[c].w - mub) * rb + b4.w;
            yp[(size_t)(it * 2) * 128 + c * 32 + l] = oa;
            yp[(size_t)(it * 2 + 1) * 128 + c * 32 + l] = ob;
        }
    }
}

// ---------------------------------------------------------------------------
extern "C" void kernel_launch(void* const* d_in, const int* in_sizes, int n_in,
                              void* d_out, int out_size) {
    const float* x     = (const float*)d_in[0];
    const float* Wp    = (const float*)d_in[1];
    const float* bp    = (const float*)d_in[2];
    const float* Wm    = (const float*)d_in[3];
    const float* bm    = (const float*)d_in[4];
    const float* Wo    = (const float*)d_in[5];
    const float* bo    = (const float*)d_in[6];
    const float* gamma = (const float*)d_in[7];
    const float* beta  = (const float*)d_in[8];
    float* y = (float*)d_out;

    dim3 g1(SS, BB);
    k_partial<<<g1, 128>>>(x);
    k_prep<<<BB, 512>>>(Wm, bm, Wo, bp, bo);
    dim3 g3(NN / 256, BB);
    k_main<<<g3, 256>>>(x, Wp, gamma, beta, y);
}